// round 5
// baseline (speedup 1.0000x reference)
#include <cuda_runtime.h>
#include <math.h>

// Problem constants
#define NB 4
#define NS 2048
#define ND 512
#define NROWS (NB * NS)   // 8192

// ---------------- device scratch (allocation-free contract) ----------------
__device__ float g_q[NROWS * ND];
__device__ float g_k[NROWS * ND];
__device__ float g_v[NROWS * ND];
__device__ float g_attn[(size_t)NROWS * NS];      // 64 MB
__device__ float g_qsq[NROWS];
__device__ float g_ksq[NROWS];
__device__ float g_colpart[8][NROWS];             // deterministic 2-stage col sums
__device__ float g_w[NROWS];                      // N_C^{-1/2}
__device__ float g_invden[NROWS];                 // 1 / sum_t(attn*w)
__device__ float g_probs_scr[(size_t)NROWS * NS]; // fallback if probs not an output
__device__ float g_out_scr[NROWS * ND];           // fallback if out not an output

// ---------------- helpers ----------------
__device__ __forceinline__ float blockReduce256(float v) {
    __shared__ float sb[8];
    int lane = threadIdx.x & 31;
    int w = threadIdx.x >> 5;
    #pragma unroll
    for (int o = 16; o > 0; o >>= 1) v += __shfl_down_sync(0xffffffffu, v, o);
    if (lane == 0) sb[w] = v;
    __syncthreads();
    float r = 0.f;
    if (threadIdx.x == 0) {
        #pragma unroll
        for (int i = 0; i < 8; i++) r += sb[i];
    }
    __syncthreads();   // protect sb reuse across calls
    return r;          // valid in thread 0 only
}

// ---------------- kernel 1: fused QKV projection (GEMM C = X * W^T + b) ----
// X: (8192, 512) row-major.  W: (512, 512) row-major (rows = output features).
// grid: (N/128=4, M/128=64, 3)   block: 256
__global__ __launch_bounds__(256) void proj_kernel(
    const float* __restrict__ x,
    const float* __restrict__ Wq, const float* __restrict__ bq,
    const float* __restrict__ Wk, const float* __restrict__ bk,
    const float* __restrict__ Wv, const float* __restrict__ bv)
{
    const int z = blockIdx.z;
    const float* W    = (z == 0) ? Wq : (z == 1) ? Wk : Wv;
    const float* bias = (z == 0) ? bq : (z == 1) ? bk : bv;
    float* out        = (z == 0) ? g_q : (z == 1) ? g_k : g_v;

    __shared__ float As[8][128];
    __shared__ float Bs[8][128];

    const int tid  = threadIdx.x;
    const int m0   = blockIdx.y * 128;
    const int n0   = blockIdx.x * 128;
    const int lrow = tid >> 1;
    const int lk   = (tid & 1) * 4;
    const int cx   = tid & 15;
    const int cy   = tid >> 4;

    const float* aPtr = x + (size_t)(m0 + lrow) * ND + lk;
    const float* bPtr = W + (size_t)(n0 + lrow) * ND + lk;

    float acc[8][8];
    #pragma unroll
    for (int i = 0; i < 8; i++)
        #pragma unroll
        for (int j = 0; j < 8; j++) acc[i][j] = 0.f;

    for (int k0 = 0; k0 < ND; k0 += 8) {
        float4 av = *(const float4*)(aPtr + k0);
        float4 bv4 = *(const float4*)(bPtr + k0);
        As[lk + 0][lrow] = av.x;  As[lk + 1][lrow] = av.y;
        As[lk + 2][lrow] = av.z;  As[lk + 3][lrow] = av.w;
        Bs[lk + 0][lrow] = bv4.x; Bs[lk + 1][lrow] = bv4.y;
        Bs[lk + 2][lrow] = bv4.z; Bs[lk + 3][lrow] = bv4.w;
        __syncthreads();
        #pragma unroll
        for (int kk = 0; kk < 8; kk++) {
            float a[8], b[8];
            *(float4*)&a[0] = *(const float4*)&As[kk][cy * 8];
            *(float4*)&a[4] = *(const float4*)&As[kk][cy * 8 + 4];
            *(float4*)&b[0] = *(const float4*)&Bs[kk][cx * 8];
            *(float4*)&b[4] = *(const float4*)&Bs[kk][cx * 8 + 4];
            #pragma unroll
            for (int i = 0; i < 8; i++)
                #pragma unroll
                for (int j = 0; j < 8; j++) acc[i][j] = fmaf(a[i], b[j], acc[i][j]);
        }
        __syncthreads();
    }

    float bb[8];
    #pragma unroll
    for (int j = 0; j < 8; j++) bb[j] = bias[n0 + cx * 8 + j];

    #pragma unroll
    for (int i = 0; i < 8; i++) {
        int gm = m0 + cy * 8 + i;
        float* orow = out + (size_t)gm * ND + n0 + cx * 8;
        float4 r0, r1;
        r0.x = acc[i][0] + bb[0]; r0.y = acc[i][1] + bb[1];
        r0.z = acc[i][2] + bb[2]; r0.w = acc[i][3] + bb[3];
        r1.x = acc[i][4] + bb[4]; r1.y = acc[i][5] + bb[5];
        r1.z = acc[i][6] + bb[6]; r1.w = acc[i][7] + bb[7];
        *(float4*)(orow)     = r0;
        *(float4*)(orow + 4) = r1;
    }
}

// ---------------- kernel 2: per-row |q|^2, |k|^2 ----------------
// grid: 8192, block: 256
__global__ __launch_bounds__(256) void sumsq_kernel() {
    int r = blockIdx.x;
    const float* qr = g_q + (size_t)r * ND;
    const float* kr = g_k + (size_t)r * ND;
    int t = threadIdx.x;
    float q0 = qr[t], q1 = qr[t + 256];
    float k0 = kr[t], k1 = kr[t + 256];
    float vq = fmaf(q0, q0, q1 * q1);
    float vk = fmaf(k0, k0, k1 * k1);
    float sq = blockReduce256(vq);
    float sk = blockReduce256(vk);
    if (threadIdx.x == 0) { g_qsq[r] = sq; g_ksq[r] = sk; }
}

// ---------------- kernel 3: attention scores ----------------
// attn[b,i,j] = exp(-max(|q_i|^2+|k_j|^2-2 q_i.k_j, eps)/512)
// grid: (16, 16, 4)   block: 256
__global__ __launch_bounds__(256) void scores_kernel() {
    const int b  = blockIdx.z;
    const int i0 = blockIdx.y * 128;
    const int j0 = blockIdx.x * 128;
    const float* qb = g_q + (size_t)b * NS * ND;
    const float* kb = g_k + (size_t)b * NS * ND;

    __shared__ float As[8][128];
    __shared__ float Bs[8][128];

    const int tid  = threadIdx.x;
    const int lrow = tid >> 1;
    const int lk   = (tid & 1) * 4;
    const int cx   = tid & 15;
    const int cy   = tid >> 4;

    const float* aPtr = qb + (size_t)(i0 + lrow) * ND + lk;
    const float* bPtr = kb + (size_t)(j0 + lrow) * ND + lk;

    float acc[8][8];
    #pragma unroll
    for (int i = 0; i < 8; i++)
        #pragma unroll
        for (int j = 0; j < 8; j++) acc[i][j] = 0.f;

    for (int k0 = 0; k0 < ND; k0 += 8) {
        float4 av = *(const float4*)(aPtr + k0);
        float4 bv4 = *(const float4*)(bPtr + k0);
        As[lk + 0][lrow] = av.x;  As[lk + 1][lrow] = av.y;
        As[lk + 2][lrow] = av.z;  As[lk + 3][lrow] = av.w;
        Bs[lk + 0][lrow] = bv4.x; Bs[lk + 1][lrow] = bv4.y;
        Bs[lk + 2][lrow] = bv4.z; Bs[lk + 3][lrow] = bv4.w;
        __syncthreads();
        #pragma unroll
        for (int kk = 0; kk < 8; kk++) {
            float a[8], bvv[8];
            *(float4*)&a[0]   = *(const float4*)&As[kk][cy * 8];
            *(float4*)&a[4]   = *(const float4*)&As[kk][cy * 8 + 4];
            *(float4*)&bvv[0] = *(const float4*)&Bs[kk][cx * 8];
            *(float4*)&bvv[4] = *(const float4*)&Bs[kk][cx * 8 + 4];
            #pragma unroll
            for (int i = 0; i < 8; i++)
                #pragma unroll
                for (int j = 0; j < 8; j++) acc[i][j] = fmaf(a[i], bvv[j], acc[i][j]);
        }
        __syncthreads();
    }

    float qsql[8], ksql[8];
    #pragma unroll
    for (int i = 0; i < 8; i++) qsql[i] = g_qsq[b * NS + i0 + cy * 8 + i];
    #pragma unroll
    for (int j = 0; j < 8; j++) ksql[j] = g_ksq[b * NS + j0 + cx * 8 + j];

    #pragma unroll
    for (int i = 0; i < 8; i++) {
        float e[8];
        #pragma unroll
        for (int j = 0; j < 8; j++) {
            float sq = qsql[i] + ksql[j] - 2.f * acc[i][j];
            sq = fmaxf(sq, 1e-12f);
            e[j] = expf(-sq * (1.f / 512.f));
        }
        size_t base = ((size_t)(b * NS + i0 + cy * 8 + i)) * NS + j0 + cx * 8;
        float4 r0 = make_float4(e[0], e[1], e[2], e[3]);
        float4 r1 = make_float4(e[4], e[5], e[6], e[7]);
        *(float4*)(g_attn + base)     = r0;
        *(float4*)(g_attn + base + 4) = r1;
    }
}

// ---------------- kernel 4: partial column sums (deterministic) ----------
// grid: (NS/256=8, 8 row-chunks, 4 batches)  block: 256
__global__ __launch_bounds__(256) void colpart_kernel() {
    int b  = blockIdx.z;
    int rc = blockIdx.y;
    int c  = blockIdx.x * 256 + threadIdx.x;
    const float* ab = g_attn + (size_t)b * NS * NS;
    float s = 0.f;
    int r0 = rc * 256;
    for (int i = 0; i < 256; i++) s += ab[(size_t)(r0 + i) * NS + c];
    g_colpart[rc][b * NS + c] = s;
}

// ---------------- kernel 5: w = N_C^{-1/2} ----------------
__global__ void w_kernel() {
    int i = blockIdx.x * blockDim.x + threadIdx.x;
    if (i < NROWS) {
        float s = 0.f;
        #pragma unroll
        for (int rc = 0; rc < 8; rc++) s += g_colpart[rc][i];
        g_w[i] = 1.0f / sqrtf(s);
    }
}

// ---------------- kernel 6: row denominators ----------------
// grid: 8192, block: 256
__global__ __launch_bounds__(256) void denom_kernel() {
    int row = blockIdx.x;
    int b = row >> 11;
    const float* ar = g_attn + (size_t)row * NS;
    const float* wr = g_w + b * NS;
    float s = 0.f;
    #pragma unroll
    for (int k = 0; k < 8; k++) {
        int t = threadIdx.x + k * 256;
        s = fmaf(ar[t], wr[t], s);
    }
    float tot = blockReduce256(s);
    if (threadIdx.x == 0) g_invden[row] = 1.0f / tot;
}

// ---------------- kernel 7: probs = attn * w[t] * invden[i] ----------------
// grid: 16384, block: 256 (float4 per thread)
__global__ __launch_bounds__(256) void probs_kernel(float* __restrict__ probs) {
    size_t idx4 = (size_t)blockIdx.x * blockDim.x + threadIdx.x;
    size_t idx = idx4 * 4;
    int row = (int)(idx >> 11);
    int t   = (int)(idx & 2047);
    int b   = row >> 11;
    float4 a  = *(const float4*)(g_attn + idx);
    float4 wv = *(const float4*)(g_w + b * NS + t);
    float inv = g_invden[row];
    float4 p;
    p.x = a.x * wv.x * inv;
    p.y = a.y * wv.y * inv;
    p.z = a.z * wv.z * inv;
    p.w = a.w * wv.w * inv;
    *(float4*)(probs + idx) = p;
}

// ---------------- kernel 8: out = probs @ v ----------------
// grid: (ND/128=4, NS/128=16, 4)  block: 256
__global__ __launch_bounds__(256) void pv_kernel(const float* __restrict__ probs,
                                                 float* __restrict__ outp) {
    const int b  = blockIdx.z;
    const int m0 = blockIdx.y * 128;
    const int n0 = blockIdx.x * 128;
    const float* A = probs + (size_t)b * NS * NS;   // [m][t]
    const float* V = g_v + (size_t)b * NS * ND;     // [t][d]

    __shared__ float As[8][128];
    __shared__ float Bs[8][128];

    const int tid  = threadIdx.x;
    const int lrow = tid >> 1;
    const int lk   = (tid & 1) * 4;
    const int brow = tid >> 5;          // 0..7  (k of Bs)
    const int bcol = (tid & 31) * 4;    // 0..124
    const int cx   = tid & 15;
    const int cy   = tid >> 4;

    float acc[8][8];
    #pragma unroll
    for (int i = 0; i < 8; i++)
        #pragma unroll
        for (int j = 0; j < 8; j++) acc[i][j] = 0.f;

    for (int t0 = 0; t0 < NS; t0 += 8) {
        float4 av = *(const float4*)(A + (size_t)(m0 + lrow) * NS + t0 + lk);
        float4 vv = *(const float4*)(V + (size_t)(t0 + brow) * ND + n0 + bcol);
        As[lk + 0][lrow] = av.x; As[lk + 1][lrow] = av.y;
        As[lk + 2][lrow] = av.z; As[lk + 3][lrow] = av.w;
        *(float4*)&Bs[brow][bcol] = vv;
        __syncthreads();
        #pragma unroll
        for (int kk = 0; kk < 8; kk++) {
            float a[8], bvv[8];
            *(float4*)&a[0]   = *(const float4*)&As[kk][cy * 8];
            *(float4*)&a[4]   = *(const float4*)&As[kk][cy * 8 + 4];
            *(float4*)&bvv[0] = *(const float4*)&Bs[kk][cx * 8];
            *(float4*)&bvv[4] = *(const float4*)&Bs[kk][cx * 8 + 4];
            #pragma unroll
            for (int i = 0; i < 8; i++)
                #pragma unroll
                for (int j = 0; j < 8; j++) acc[i][j] = fmaf(a[i], bvv[j], acc[i][j]);
        }
        __syncthreads();
    }

    #pragma unroll
    for (int i = 0; i < 8; i++) {
        int gm = b * NS + m0 + cy * 8 + i;
        float* orow = outp + (size_t)gm * ND + n0 + cx * 8;
        float4 r0 = make_float4(acc[i][0], acc[i][1], acc[i][2], acc[i][3]);
        float4 r1 = make_float4(acc[i][4], acc[i][5], acc[i][6], acc[i][7]);
        *(float4*)(orow)     = r0;
        *(float4*)(orow + 4) = r1;
    }
}

// ---------------- launch ----------------
extern "C" void kernel_launch(void* const* d_in, const int* in_sizes, int n_in,
                              void* d_out, int out_size) {
    const float* x  = (const float*)d_in[0];
    const float* Wq = (const float*)d_in[1];
    const float* bq = (const float*)d_in[2];
    const float* Wk = (const float*)d_in[3];
    const float* bk = (const float*)d_in[4];
    const float* Wv = (const float*)d_in[5];
    const float* bv = (const float*)d_in[6];
    float* out = (float*)d_out;

    const long long OUT_E = (long long)NB * NS * ND;  //  4,194,304
    const long long PR_E  = (long long)NB * NS * NS;  // 16,777,216

    float* probs_scr = nullptr;
    float* out_scr = nullptr;
    cudaGetSymbolAddress((void**)&probs_scr, g_probs_scr);
    cudaGetSymbolAddress((void**)&out_scr, g_out_scr);

    float* out_ptr;
    float* probs_ptr;
    if ((long long)out_size >= OUT_E + PR_E) {        // tuple (out, probs) flattened
        out_ptr = out; probs_ptr = out + OUT_E;
    } else if ((long long)out_size == OUT_E) {        // only out compared
        out_ptr = out; probs_ptr = probs_scr;
    } else if ((long long)out_size == PR_E) {         // only probs compared
        out_ptr = out_scr; probs_ptr = out;
    } else {
        out_ptr = out; probs_ptr = out + OUT_E;
    }

    proj_kernel<<<dim3(4, 64, 3), 256>>>(x, Wq, bq, Wk, bk, Wv, bv);
    sumsq_kernel<<<NROWS, 256>>>();
    scores_kernel<<<dim3(16, 16, 4), 256>>>();
    colpart_kernel<<<dim3(8, 8, 4), 256>>>();
    w_kernel<<<32, 256>>>();
    denom_kernel<<<NROWS, 256>>>();
    probs_kernel<<<16384, 256>>>(probs_ptr);
    pv_kernel<<<dim3(4, 16, 4), 256>>>(probs_ptr, out_ptr);
}

// round 6
// speedup vs baseline: 1.0011x; 1.0011x over previous
#include <cuda_runtime.h>
#include <math.h>

// Problem constants
#define NB 4
#define NS 2048
#define ND 512
#define NROWS (NB * NS)   // 8192

// ---------------- device scratch (allocation-free contract) ----------------
__device__ float g_q[NROWS * ND];
__device__ float g_k[NROWS * ND];
__device__ float g_v[NROWS * ND];
__device__ float g_attn[(size_t)NROWS * NS];      // 64 MB
__device__ float g_qsq[NROWS];
__device__ float g_ksq[NROWS];
__device__ float g_colpart[8][NROWS];             // deterministic 2-stage col sums
__device__ float g_w[NROWS];                      // N_C^{-1/2}
__device__ float g_invden[NROWS];                 // 1 / sum_t(attn*w)
__device__ float g_probs_scr[(size_t)NROWS * NS]; // fallback if probs not an output
__device__ float g_out_scr[NROWS * ND];           // fallback if out not an output

// ---------------- helpers ----------------
__device__ __forceinline__ float blockReduce256(float v) {
    __shared__ float sb[8];
    int lane = threadIdx.x & 31;
    int w = threadIdx.x >> 5;
    #pragma unroll
    for (int o = 16; o > 0; o >>= 1) v += __shfl_down_sync(0xffffffffu, v, o);
    if (lane == 0) sb[w] = v;
    __syncthreads();
    float r = 0.f;
    if (threadIdx.x == 0) {
        #pragma unroll
        for (int i = 0; i < 8; i++) r += sb[i];
    }
    __syncthreads();   // protect sb reuse across calls
    return r;          // valid in thread 0 only
}

// ---------------- kernel 1: fused QKV projection (GEMM C = X * W^T + b) ----
// X: (8192, 512) row-major.  W: (512, 512) row-major (rows = output features).
// grid: (N/128=4, M/128=64, 3)   block: 256
__global__ __launch_bounds__(256) void proj_kernel(
    const float* __restrict__ x,
    const float* __restrict__ Wq, const float* __restrict__ bq,
    const float* __restrict__ Wk, const float* __restrict__ bk,
    const float* __restrict__ Wv, const float* __restrict__ bv)
{
    const int z = blockIdx.z;
    const float* W    = (z == 0) ? Wq : (z == 1) ? Wk : Wv;
    const float* bias = (z == 0) ? bq : (z == 1) ? bk : bv;
    float* out        = (z == 0) ? g_q : (z == 1) ? g_k : g_v;

    __shared__ float As[8][128];
    __shared__ float Bs[8][128];

    const int tid  = threadIdx.x;
    const int m0   = blockIdx.y * 128;
    const int n0   = blockIdx.x * 128;
    const int lrow = tid >> 1;
    const int lk   = (tid & 1) * 4;
    const int cx   = tid & 15;
    const int cy   = tid >> 4;

    const float* aPtr = x + (size_t)(m0 + lrow) * ND + lk;
    const float* bPtr = W + (size_t)(n0 + lrow) * ND + lk;

    float acc[8][8];
    #pragma unroll
    for (int i = 0; i < 8; i++)
        #pragma unroll
        for (int j = 0; j < 8; j++) acc[i][j] = 0.f;

    for (int k0 = 0; k0 < ND; k0 += 8) {
        float4 av = *(const float4*)(aPtr + k0);
        float4 bv4 = *(const float4*)(bPtr + k0);
        As[lk + 0][lrow] = av.x;  As[lk + 1][lrow] = av.y;
        As[lk + 2][lrow] = av.z;  As[lk + 3][lrow] = av.w;
        Bs[lk + 0][lrow] = bv4.x; Bs[lk + 1][lrow] = bv4.y;
        Bs[lk + 2][lrow] = bv4.z; Bs[lk + 3][lrow] = bv4.w;
        __syncthreads();
        #pragma unroll
        for (int kk = 0; kk < 8; kk++) {
            float a[8], b[8];
            *(float4*)&a[0] = *(const float4*)&As[kk][cy * 8];
            *(float4*)&a[4] = *(const float4*)&As[kk][cy * 8 + 4];
            *(float4*)&b[0] = *(const float4*)&Bs[kk][cx * 8];
            *(float4*)&b[4] = *(const float4*)&Bs[kk][cx * 8 + 4];
            #pragma unroll
            for (int i = 0; i < 8; i++)
                #pragma unroll
                for (int j = 0; j < 8; j++) acc[i][j] = fmaf(a[i], b[j], acc[i][j]);
        }
        __syncthreads();
    }

    float bb[8];
    #pragma unroll
    for (int j = 0; j < 8; j++) bb[j] = bias[n0 + cx * 8 + j];

    #pragma unroll
    for (int i = 0; i < 8; i++) {
        int gm = m0 + cy * 8 + i;
        float* orow = out + (size_t)gm * ND + n0 + cx * 8;
        float4 r0, r1;
        r0.x = acc[i][0] + bb[0]; r0.y = acc[i][1] + bb[1];
        r0.z = acc[i][2] + bb[2]; r0.w = acc[i][3] + bb[3];
        r1.x = acc[i][4] + bb[4]; r1.y = acc[i][5] + bb[5];
        r1.z = acc[i][6] + bb[6]; r1.w = acc[i][7] + bb[7];
        *(float4*)(orow)     = r0;
        *(float4*)(orow + 4) = r1;
    }
}

// ---------------- kernel 2: per-row |q|^2, |k|^2 ----------------
// grid: 8192, block: 256
__global__ __launch_bounds__(256) void sumsq_kernel() {
    int r = blockIdx.x;
    const float* qr = g_q + (size_t)r * ND;
    const float* kr = g_k + (size_t)r * ND;
    int t = threadIdx.x;
    float q0 = qr[t], q1 = qr[t + 256];
    float k0 = kr[t], k1 = kr[t + 256];
    float vq = fmaf(q0, q0, q1 * q1);
    float vk = fmaf(k0, k0, k1 * k1);
    float sq = blockReduce256(vq);
    float sk = blockReduce256(vk);
    if (threadIdx.x == 0) { g_qsq[r] = sq; g_ksq[r] = sk; }
}

// ---------------- kernel 3: attention scores ----------------
// attn[b,i,j] = exp(-max(|q_i|^2+|k_j|^2-2 q_i.k_j, eps)/512)
// grid: (16, 16, 4)   block: 256
__global__ __launch_bounds__(256) void scores_kernel() {
    const int b  = blockIdx.z;
    const int i0 = blockIdx.y * 128;
    const int j0 = blockIdx.x * 128;
    const float* qb = g_q + (size_t)b * NS * ND;
    const float* kb = g_k + (size_t)b * NS * ND;

    __shared__ float As[8][128];
    __shared__ float Bs[8][128];

    const int tid  = threadIdx.x;
    const int lrow = tid >> 1;
    const int lk   = (tid & 1) * 4;
    const int cx   = tid & 15;
    const int cy   = tid >> 4;

    const float* aPtr = qb + (size_t)(i0 + lrow) * ND + lk;
    const float* bPtr = kb + (size_t)(j0 + lrow) * ND + lk;

    float acc[8][8];
    #pragma unroll
    for (int i = 0; i < 8; i++)
        #pragma unroll
        for (int j = 0; j < 8; j++) acc[i][j] = 0.f;

    for (int k0 = 0; k0 < ND; k0 += 8) {
        float4 av = *(const float4*)(aPtr + k0);
        float4 bv4 = *(const float4*)(bPtr + k0);
        As[lk + 0][lrow] = av.x;  As[lk + 1][lrow] = av.y;
        As[lk + 2][lrow] = av.z;  As[lk + 3][lrow] = av.w;
        Bs[lk + 0][lrow] = bv4.x; Bs[lk + 1][lrow] = bv4.y;
        Bs[lk + 2][lrow] = bv4.z; Bs[lk + 3][lrow] = bv4.w;
        __syncthreads();
        #pragma unroll
        for (int kk = 0; kk < 8; kk++) {
            float a[8], bvv[8];
            *(float4*)&a[0]   = *(const float4*)&As[kk][cy * 8];
            *(float4*)&a[4]   = *(const float4*)&As[kk][cy * 8 + 4];
            *(float4*)&bvv[0] = *(const float4*)&Bs[kk][cx * 8];
            *(float4*)&bvv[4] = *(const float4*)&Bs[kk][cx * 8 + 4];
            #pragma unroll
            for (int i = 0; i < 8; i++)
                #pragma unroll
                for (int j = 0; j < 8; j++) acc[i][j] = fmaf(a[i], bvv[j], acc[i][j]);
        }
        __syncthreads();
    }

    float qsql[8], ksql[8];
    #pragma unroll
    for (int i = 0; i < 8; i++) qsql[i] = g_qsq[b * NS + i0 + cy * 8 + i];
    #pragma unroll
    for (int j = 0; j < 8; j++) ksql[j] = g_ksq[b * NS + j0 + cx * 8 + j];

    #pragma unroll
    for (int i = 0; i < 8; i++) {
        float e[8];
        #pragma unroll
        for (int j = 0; j < 8; j++) {
            float sq = qsql[i] + ksql[j] - 2.f * acc[i][j];
            sq = fmaxf(sq, 1e-12f);
            e[j] = expf(-sq * (1.f / 512.f));
        }
        size_t base = ((size_t)(b * NS + i0 + cy * 8 + i)) * NS + j0 + cx * 8;
        float4 r0 = make_float4(e[0], e[1], e[2], e[3]);
        float4 r1 = make_float4(e[4], e[5], e[6], e[7]);
        *(float4*)(g_attn + base)     = r0;
        *(float4*)(g_attn + base + 4) = r1;
    }
}

// ---------------- kernel 4: partial column sums (deterministic) ----------
// grid: (NS/256=8, 8 row-chunks, 4 batches)  block: 256
__global__ __launch_bounds__(256) void colpart_kernel() {
    int b  = blockIdx.z;
    int rc = blockIdx.y;
    int c  = blockIdx.x * 256 + threadIdx.x;
    const float* ab = g_attn + (size_t)b * NS * NS;
    float s = 0.f;
    int r0 = rc * 256;
    for (int i = 0; i < 256; i++) s += ab[(size_t)(r0 + i) * NS + c];
    g_colpart[rc][b * NS + c] = s;
}

// ---------------- kernel 5: w = N_C^{-1/2} ----------------
__global__ void w_kernel() {
    int i = blockIdx.x * blockDim.x + threadIdx.x;
    if (i < NROWS) {
        float s = 0.f;
        #pragma unroll
        for (int rc = 0; rc < 8; rc++) s += g_colpart[rc][i];
        g_w[i] = 1.0f / sqrtf(s);
    }
}

// ---------------- kernel 6: row denominators ----------------
// grid: 8192, block: 256
__global__ __launch_bounds__(256) void denom_kernel() {
    int row = blockIdx.x;
    int b = row >> 11;
    const float* ar = g_attn + (size_t)row * NS;
    const float* wr = g_w + b * NS;
    float s = 0.f;
    #pragma unroll
    for (int k = 0; k < 8; k++) {
        int t = threadIdx.x + k * 256;
        s = fmaf(ar[t], wr[t], s);
    }
    float tot = blockReduce256(s);
    if (threadIdx.x == 0) g_invden[row] = 1.0f / tot;
}

// ---------------- kernel 7: probs = attn * w[t] * invden[i] ----------------
// grid: 16384, block: 256 (float4 per thread)
__global__ __launch_bounds__(256) void probs_kernel(float* __restrict__ probs) {
    size_t idx4 = (size_t)blockIdx.x * blockDim.x + threadIdx.x;
    size_t idx = idx4 * 4;
    int row = (int)(idx >> 11);
    int t   = (int)(idx & 2047);
    int b   = row >> 11;
    float4 a  = *(const float4*)(g_attn + idx);
    float4 wv = *(const float4*)(g_w + b * NS + t);
    float inv = g_invden[row];
    float4 p;
    p.x = a.x * wv.x * inv;
    p.y = a.y * wv.y * inv;
    p.z = a.z * wv.z * inv;
    p.w = a.w * wv.w * inv;
    *(float4*)(probs + idx) = p;
}

// ---------------- kernel 8: out = probs @ v ----------------
// grid: (ND/128=4, NS/128=16, 4)  block: 256
__global__ __launch_bounds__(256) void pv_kernel(const float* __restrict__ probs,
                                                 float* __restrict__ outp) {
    const int b  = blockIdx.z;
    const int m0 = blockIdx.y * 128;
    const int n0 = blockIdx.x * 128;
    const float* A = probs + (size_t)b * NS * NS;   // [m][t]
    const float* V = g_v + (size_t)b * NS * ND;     // [t][d]

    __shared__ float As[8][128];
    __shared__ float Bs[8][128];

    const int tid  = threadIdx.x;
    const int lrow = tid >> 1;
    const int lk   = (tid & 1) * 4;
    const int brow = tid >> 5;          // 0..7  (k of Bs)
    const int bcol = (tid & 31) * 4;    // 0..124
    const int cx   = tid & 15;
    const int cy   = tid >> 4;

    float acc[8][8];
    #pragma unroll
    for (int i = 0; i < 8; i++)
        #pragma unroll
        for (int j = 0; j < 8; j++) acc[i][j] = 0.f;

    for (int t0 = 0; t0 < NS; t0 += 8) {
        float4 av = *(const float4*)(A + (size_t)(m0 + lrow) * NS + t0 + lk);
        float4 vv = *(const float4*)(V + (size_t)(t0 + brow) * ND + n0 + bcol);
        As[lk + 0][lrow] = av.x; As[lk + 1][lrow] = av.y;
        As[lk + 2][lrow] = av.z; As[lk + 3][lrow] = av.w;
        *(float4*)&Bs[brow][bcol] = vv;
        __syncthreads();
        #pragma unroll
        for (int kk = 0; kk < 8; kk++) {
            float a[8], bvv[8];
            *(float4*)&a[0]   = *(const float4*)&As[kk][cy * 8];
            *(float4*)&a[4]   = *(const float4*)&As[kk][cy * 8 + 4];
            *(float4*)&bvv[0] = *(const float4*)&Bs[kk][cx * 8];
            *(float4*)&bvv[4] = *(const float4*)&Bs[kk][cx * 8 + 4];
            #pragma unroll
            for (int i = 0; i < 8; i++)
                #pragma unroll
                for (int j = 0; j < 8; j++) acc[i][j] = fmaf(a[i], bvv[j], acc[i][j]);
        }
        __syncthreads();
    }

    #pragma unroll
    for (int i = 0; i < 8; i++) {
        int gm = b * NS + m0 + cy * 8 + i;
        float* orow = outp + (size_t)gm * ND + n0 + cx * 8;
        float4 r0 = make_float4(acc[i][0], acc[i][1], acc[i][2], acc[i][3]);
        float4 r1 = make_float4(acc[i][4], acc[i][5], acc[i][6], acc[i][7]);
        *(float4*)(orow)     = r0;
        *(float4*)(orow + 4) = r1;
    }
}

// ---------------- launch ----------------
extern "C" void kernel_launch(void* const* d_in, const int* in_sizes, int n_in,
                              void* d_out, int out_size) {
    const float* x  = (const float*)d_in[0];
    const float* Wq = (const float*)d_in[1];
    const float* bq = (const float*)d_in[2];
    const float* Wk = (const float*)d_in[3];
    const float* bk = (const float*)d_in[4];
    const float* Wv = (const float*)d_in[5];
    const float* bv = (const float*)d_in[6];
    float* out = (float*)d_out;

    const long long OUT_E = (long long)NB * NS * ND;  //  4,194,304
    const long long PR_E  = (long long)NB * NS * NS;  // 16,777,216

    float* probs_scr = nullptr;
    float* out_scr = nullptr;
    cudaGetSymbolAddress((void**)&probs_scr, g_probs_scr);
    cudaGetSymbolAddress((void**)&out_scr, g_out_scr);

    float* out_ptr;
    float* probs_ptr;
    if ((long long)out_size >= OUT_E + PR_E) {        // tuple (out, probs) flattened
        out_ptr = out; probs_ptr = out + OUT_E;
    } else if ((long long)out_size == OUT_E) {        // only out compared
        out_ptr = out; probs_ptr = probs_scr;
    } else if ((long long)out_size == PR_E) {         // only probs compared
        out_ptr = out_scr; probs_ptr = out;
    } else {
        out_ptr = out; probs_ptr = out + OUT_E;
    }

    proj_kernel<<<dim3(4, 64, 3), 256>>>(x, Wq, bq, Wk, bk, Wv, bv);
    sumsq_kernel<<<NROWS, 256>>>();
    scores_kernel<<<dim3(16, 16, 4), 256>>>();
    colpart_kernel<<<dim3(8, 8, 4), 256>>>();
    w_kernel<<<32, 256>>>();
    denom_kernel<<<NROWS, 256>>>();
    probs_kernel<<<16384, 256>>>(probs_ptr);
    pv_kernel<<<dim3(4, 16, 4), 256>>>(probs_ptr, out_ptr);
}

// round 7
// speedup vs baseline: 1.0083x; 1.0072x over previous
#include <cuda_runtime.h>
#include <math.h>

// Problem constants
#define NB 4
#define NS 2048
#define ND 512
#define NROWS (NB * NS)   // 8192

// ---------------- device scratch (allocation-free contract) ----------------
__device__ float g_q[NROWS * ND];
__device__ float g_k[NROWS * ND];
__device__ float g_v[NROWS * ND];
__device__ float g_attn[(size_t)NROWS * NS];      // 64 MB
__device__ float g_qsq[NROWS];
__device__ float g_ksq[NROWS];
__device__ float g_colpart[8][NROWS];             // deterministic 2-stage col sums
__device__ float g_w[NROWS];                      // N_C^{-1/2}
__device__ float g_invden[NROWS];                 // 1 / sum_t(attn*w)
__device__ float g_probs_scr[(size_t)NROWS * NS]; // fallback if probs not an output
__device__ float g_out_scr[NROWS * ND];           // fallback if out not an output

// ---------------- helpers ----------------
__device__ __forceinline__ float blockReduce256(float v) {
    __shared__ float sb[8];
    int lane = threadIdx.x & 31;
    int w = threadIdx.x >> 5;
    #pragma unroll
    for (int o = 16; o > 0; o >>= 1) v += __shfl_down_sync(0xffffffffu, v, o);
    if (lane == 0) sb[w] = v;
    __syncthreads();
    float r = 0.f;
    if (threadIdx.x == 0) {
        #pragma unroll
        for (int i = 0; i < 8; i++) r += sb[i];
    }
    __syncthreads();   // protect sb reuse across calls
    return r;          // valid in thread 0 only
}

// ---------------- kernel 1: fused QKV projection (GEMM C = X * W^T + b) ----
// X: (8192, 512) row-major.  W: (512, 512) row-major (rows = output features).
// grid: (N/128=4, M/128=64, 3)   block: 256
__global__ __launch_bounds__(256) void proj_kernel(
    const float* __restrict__ x,
    const float* __restrict__ Wq, const float* __restrict__ bq,
    const float* __restrict__ Wk, const float* __restrict__ bk,
    const float* __restrict__ Wv, const float* __restrict__ bv)
{
    const int z = blockIdx.z;
    const float* W    = (z == 0) ? Wq : (z == 1) ? Wk : Wv;
    const float* bias = (z == 0) ? bq : (z == 1) ? bk : bv;
    float* out        = (z == 0) ? g_q : (z == 1) ? g_k : g_v;

    __shared__ float As[8][128];
    __shared__ float Bs[8][128];

    const int tid  = threadIdx.x;
    const int m0   = blockIdx.y * 128;
    const int n0   = blockIdx.x * 128;
    const int lrow = tid >> 1;
    const int lk   = (tid & 1) * 4;
    const int cx   = tid & 15;
    const int cy   = tid >> 4;

    const float* aPtr = x + (size_t)(m0 + lrow) * ND + lk;
    const float* bPtr = W + (size_t)(n0 + lrow) * ND + lk;

    float acc[8][8];
    #pragma unroll
    for (int i = 0; i < 8; i++)
        #pragma unroll
        for (int j = 0; j < 8; j++) acc[i][j] = 0.f;

    for (int k0 = 0; k0 < ND; k0 += 8) {
        float4 av = *(const float4*)(aPtr + k0);
        float4 bv4 = *(const float4*)(bPtr + k0);
        As[lk + 0][lrow] = av.x;  As[lk + 1][lrow] = av.y;
        As[lk + 2][lrow] = av.z;  As[lk + 3][lrow] = av.w;
        Bs[lk + 0][lrow] = bv4.x; Bs[lk + 1][lrow] = bv4.y;
        Bs[lk + 2][lrow] = bv4.z; Bs[lk + 3][lrow] = bv4.w;
        __syncthreads();
        #pragma unroll
        for (int kk = 0; kk < 8; kk++) {
            float a[8], b[8];
            *(float4*)&a[0] = *(const float4*)&As[kk][cy * 8];
            *(float4*)&a[4] = *(const float4*)&As[kk][cy * 8 + 4];
            *(float4*)&b[0] = *(const float4*)&Bs[kk][cx * 8];
            *(float4*)&b[4] = *(const float4*)&Bs[kk][cx * 8 + 4];
            #pragma unroll
            for (int i = 0; i < 8; i++)
                #pragma unroll
                for (int j = 0; j < 8; j++) acc[i][j] = fmaf(a[i], b[j], acc[i][j]);
        }
        __syncthreads();
    }

    float bb[8];
    #pragma unroll
    for (int j = 0; j < 8; j++) bb[j] = bias[n0 + cx * 8 + j];

    #pragma unroll
    for (int i = 0; i < 8; i++) {
        int gm = m0 + cy * 8 + i;
        float* orow = out + (size_t)gm * ND + n0 + cx * 8;
        float4 r0, r1;
        r0.x = acc[i][0] + bb[0]; r0.y = acc[i][1] + bb[1];
        r0.z = acc[i][2] + bb[2]; r0.w = acc[i][3] + bb[3];
        r1.x = acc[i][4] + bb[4]; r1.y = acc[i][5] + bb[5];
        r1.z = acc[i][6] + bb[6]; r1.w = acc[i][7] + bb[7];
        *(float4*)(orow)     = r0;
        *(float4*)(orow + 4) = r1;
    }
}

// ---------------- kernel 2: per-row |q|^2, |k|^2 ----------------
// grid: 8192, block: 256
__global__ __launch_bounds__(256) void sumsq_kernel() {
    int r = blockIdx.x;
    const float* qr = g_q + (size_t)r * ND;
    const float* kr = g_k + (size_t)r * ND;
    int t = threadIdx.x;
    float q0 = qr[t], q1 = qr[t + 256];
    float k0 = kr[t], k1 = kr[t + 256];
    float vq = fmaf(q0, q0, q1 * q1);
    float vk = fmaf(k0, k0, k1 * k1);
    float sq = blockReduce256(vq);
    float sk = blockReduce256(vk);
    if (threadIdx.x == 0) { g_qsq[r] = sq; g_ksq[r] = sk; }
}

// ---------------- kernel 3: attention scores ----------------
// attn[b,i,j] = exp(-max(|q_i|^2+|k_j|^2-2 q_i.k_j, eps)/512)
// grid: (16, 16, 4)   block: 256
__global__ __launch_bounds__(256) void scores_kernel() {
    const int b  = blockIdx.z;
    const int i0 = blockIdx.y * 128;
    const int j0 = blockIdx.x * 128;
    const float* qb = g_q + (size_t)b * NS * ND;
    const float* kb = g_k + (size_t)b * NS * ND;

    __shared__ float As[8][128];
    __shared__ float Bs[8][128];

    const int tid  = threadIdx.x;
    const int lrow = tid >> 1;
    const int lk   = (tid & 1) * 4;
    const int cx   = tid & 15;
    const int cy   = tid >> 4;

    const float* aPtr = qb + (size_t)(i0 + lrow) * ND + lk;
    const float* bPtr = kb + (size_t)(j0 + lrow) * ND + lk;

    float acc[8][8];
    #pragma unroll
    for (int i = 0; i < 8; i++)
        #pragma unroll
        for (int j = 0; j < 8; j++) acc[i][j] = 0.f;

    for (int k0 = 0; k0 < ND; k0 += 8) {
        float4 av = *(const float4*)(aPtr + k0);
        float4 bv4 = *(const float4*)(bPtr + k0);
        As[lk + 0][lrow] = av.x;  As[lk + 1][lrow] = av.y;
        As[lk + 2][lrow] = av.z;  As[lk + 3][lrow] = av.w;
        Bs[lk + 0][lrow] = bv4.x; Bs[lk + 1][lrow] = bv4.y;
        Bs[lk + 2][lrow] = bv4.z; Bs[lk + 3][lrow] = bv4.w;
        __syncthreads();
        #pragma unroll
        for (int kk = 0; kk < 8; kk++) {
            float a[8], bvv[8];
            *(float4*)&a[0]   = *(const float4*)&As[kk][cy * 8];
            *(float4*)&a[4]   = *(const float4*)&As[kk][cy * 8 + 4];
            *(float4*)&bvv[0] = *(const float4*)&Bs[kk][cx * 8];
            *(float4*)&bvv[4] = *(const float4*)&Bs[kk][cx * 8 + 4];
            #pragma unroll
            for (int i = 0; i < 8; i++)
                #pragma unroll
                for (int j = 0; j < 8; j++) acc[i][j] = fmaf(a[i], bvv[j], acc[i][j]);
        }
        __syncthreads();
    }

    float qsql[8], ksql[8];
    #pragma unroll
    for (int i = 0; i < 8; i++) qsql[i] = g_qsq[b * NS + i0 + cy * 8 + i];
    #pragma unroll
    for (int j = 0; j < 8; j++) ksql[j] = g_ksq[b * NS + j0 + cx * 8 + j];

    #pragma unroll
    for (int i = 0; i < 8; i++) {
        float e[8];
        #pragma unroll
        for (int j = 0; j < 8; j++) {
            float sq = qsql[i] + ksql[j] - 2.f * acc[i][j];
            sq = fmaxf(sq, 1e-12f);
            e[j] = expf(-sq * (1.f / 512.f));
        }
        size_t base = ((size_t)(b * NS + i0 + cy * 8 + i)) * NS + j0 + cx * 8;
        float4 r0 = make_float4(e[0], e[1], e[2], e[3]);
        float4 r1 = make_float4(e[4], e[5], e[6], e[7]);
        *(float4*)(g_attn + base)     = r0;
        *(float4*)(g_attn + base + 4) = r1;
    }
}

// ---------------- kernel 4: partial column sums (deterministic) ----------
// grid: (NS/256=8, 8 row-chunks, 4 batches)  block: 256
__global__ __launch_bounds__(256) void colpart_kernel() {
    int b  = blockIdx.z;
    int rc = blockIdx.y;
    int c  = blockIdx.x * 256 + threadIdx.x;
    const float* ab = g_attn + (size_t)b * NS * NS;
    float s = 0.f;
    int r0 = rc * 256;
    for (int i = 0; i < 256; i++) s += ab[(size_t)(r0 + i) * NS + c];
    g_colpart[rc][b * NS + c] = s;
}

// ---------------- kernel 5: w = N_C^{-1/2} ----------------
__global__ void w_kernel() {
    int i = blockIdx.x * blockDim.x + threadIdx.x;
    if (i < NROWS) {
        float s = 0.f;
        #pragma unroll
        for (int rc = 0; rc < 8; rc++) s += g_colpart[rc][i];
        g_w[i] = 1.0f / sqrtf(s);
    }
}

// ---------------- kernel 6: row denominators ----------------
// grid: 8192, block: 256
__global__ __launch_bounds__(256) void denom_kernel() {
    int row = blockIdx.x;
    int b = row >> 11;
    const float* ar = g_attn + (size_t)row * NS;
    const float* wr = g_w + b * NS;
    float s = 0.f;
    #pragma unroll
    for (int k = 0; k < 8; k++) {
        int t = threadIdx.x + k * 256;
        s = fmaf(ar[t], wr[t], s);
    }
    float tot = blockReduce256(s);
    if (threadIdx.x == 0) g_invden[row] = 1.0f / tot;
}

// ---------------- kernel 7: probs = attn * w[t] * invden[i] ----------------
// grid: 16384, block: 256 (float4 per thread)
__global__ __launch_bounds__(256) void probs_kernel(float* __restrict__ probs) {
    size_t idx4 = (size_t)blockIdx.x * blockDim.x + threadIdx.x;
    size_t idx = idx4 * 4;
    int row = (int)(idx >> 11);
    int t   = (int)(idx & 2047);
    int b   = row >> 11;
    float4 a  = *(const float4*)(g_attn + idx);
    float4 wv = *(const float4*)(g_w + b * NS + t);
    float inv = g_invden[row];
    float4 p;
    p.x = a.x * wv.x * inv;
    p.y = a.y * wv.y * inv;
    p.z = a.z * wv.z * inv;
    p.w = a.w * wv.w * inv;
    *(float4*)(probs + idx) = p;
}

// ---------------- kernel 8: out = probs @ v ----------------
// grid: (ND/128=4, NS/128=16, 4)  block: 256
__global__ __launch_bounds__(256) void pv_kernel(const float* __restrict__ probs,
                                                 float* __restrict__ outp) {
    const int b  = blockIdx.z;
    const int m0 = blockIdx.y * 128;
    const int n0 = blockIdx.x * 128;
    const float* A = probs + (size_t)b * NS * NS;   // [m][t]
    const float* V = g_v + (size_t)b * NS * ND;     // [t][d]

    __shared__ float As[8][128];
    __shared__ float Bs[8][128];

    const int tid  = threadIdx.x;
    const int lrow = tid >> 1;
    const int lk   = (tid & 1) * 4;
    const int brow = tid >> 5;          // 0..7  (k of Bs)
    const int bcol = (tid & 31) * 4;    // 0..124
    const int cx   = tid & 15;
    const int cy   = tid >> 4;

    float acc[8][8];
    #pragma unroll
    for (int i = 0; i < 8; i++)
        #pragma unroll
        for (int j = 0; j < 8; j++) acc[i][j] = 0.f;

    for (int t0 = 0; t0 < NS; t0 += 8) {
        float4 av = *(const float4*)(A + (size_t)(m0 + lrow) * NS + t0 + lk);
        float4 vv = *(const float4*)(V + (size_t)(t0 + brow) * ND + n0 + bcol);
        As[lk + 0][lrow] = av.x; As[lk + 1][lrow] = av.y;
        As[lk + 2][lrow] = av.z; As[lk + 3][lrow] = av.w;
        *(float4*)&Bs[brow][bcol] = vv;
        __syncthreads();
        #pragma unroll
        for (int kk = 0; kk < 8; kk++) {
            float a[8], bvv[8];
            *(float4*)&a[0]   = *(const float4*)&As[kk][cy * 8];
            *(float4*)&a[4]   = *(const float4*)&As[kk][cy * 8 + 4];
            *(float4*)&bvv[0] = *(const float4*)&Bs[kk][cx * 8];
            *(float4*)&bvv[4] = *(const float4*)&Bs[kk][cx * 8 + 4];
            #pragma unroll
            for (int i = 0; i < 8; i++)
                #pragma unroll
                for (int j = 0; j < 8; j++) acc[i][j] = fmaf(a[i], bvv[j], acc[i][j]);
        }
        __syncthreads();
    }

    #pragma unroll
    for (int i = 0; i < 8; i++) {
        int gm = b * NS + m0 + cy * 8 + i;
        float* orow = outp + (size_t)gm * ND + n0 + cx * 8;
        float4 r0 = make_float4(acc[i][0], acc[i][1], acc[i][2], acc[i][3]);
        float4 r1 = make_float4(acc[i][4], acc[i][5], acc[i][6], acc[i][7]);
        *(float4*)(orow)     = r0;
        *(float4*)(orow + 4) = r1;
    }
}

// ---------------- launch ----------------
extern "C" void kernel_launch(void* const* d_in, const int* in_sizes, int n_in,
                              void* d_out, int out_size) {
    const float* x  = (const float*)d_in[0];
    const float* Wq = (const float*)d_in[1];
    const float* bq = (const float*)d_in[2];
    const float* Wk = (const float*)d_in[3];
    const float* bk = (const float*)d_in[4];
    const float* Wv = (const float*)d_in[5];
    const float* bv = (const float*)d_in[6];
    float* out = (float*)d_out;

    const long long OUT_E = (long long)NB * NS * ND;  //  4,194,304
    const long long PR_E  = (long long)NB * NS * NS;  // 16,777,216

    float* probs_scr = nullptr;
    float* out_scr = nullptr;
    cudaGetSymbolAddress((void**)&probs_scr, g_probs_scr);
    cudaGetSymbolAddress((void**)&out_scr, g_out_scr);

    float* out_ptr;
    float* probs_ptr;
    if ((long long)out_size >= OUT_E + PR_E) {        // tuple (out, probs) flattened
        out_ptr = out; probs_ptr = out + OUT_E;
    } else if ((long long)out_size == OUT_E) {        // only out compared
        out_ptr = out; probs_ptr = probs_scr;
    } else if ((long long)out_size == PR_E) {         // only probs compared
        out_ptr = out_scr; probs_ptr = out;
    } else {
        out_ptr = out; probs_ptr = out + OUT_E;
    }

    proj_kernel<<<dim3(4, 64, 3), 256>>>(x, Wq, bq, Wk, bk, Wv, bv);
    sumsq_kernel<<<NROWS, 256>>>();
    scores_kernel<<<dim3(16, 16, 4), 256>>>();
    colpart_kernel<<<dim3(8, 8, 4), 256>>>();
    w_kernel<<<32, 256>>>();
    denom_kernel<<<NROWS, 256>>>();
    probs_kernel<<<16384, 256>>>(probs_ptr);
    pv_kernel<<<dim3(4, 16, 4), 256>>>(probs_ptr, out_ptr);
}